// round 13
// baseline (speedup 1.0000x reference)
#include <cuda_runtime.h>
#include <cuda_fp16.h>
#include <cstdint>
#include <cstddef>

#define B_ 128
#define L_ 196
#define F_ 2048
#define A_ 1024
#define H_ 1024
#define M_ (B_ * L_)   // 25088
#define NBLK 8

// ---------------- scratch (__device__ globals; no allocations) -------------
__device__ float  g_bias[B_ * A_];          // hidden@W_hid + b_hid + b_enc
__device__ float  g_part[NBLK * M_];        // partial scores per n-block
__device__ __half g_encH[M_ * F_];          // enc in fp16 (103 MB)
__device__ __half g_WtH[A_ * F_];           // W_enc^T in fp16, [N][K]

// ---------------- helpers ---------------------------------------------------
__device__ __forceinline__ uint32_t smem_u32(const void* p) {
    uint32_t r;
    asm("{ .reg .u64 t; cvta.to.shared.u64 t, %1; cvt.u32.u64 %0, t; }"
        : "=r"(r) : "l"(p));
    return r;
}
__device__ __forceinline__ void cp16(uint32_t dst, const void* src) {
    asm volatile("cp.async.cg.shared.global [%0], [%1], 16;" :: "r"(dst), "l"(src));
}
__device__ __forceinline__ void cp_commit() {
    asm volatile("cp.async.commit_group;" ::: "memory");
}
template <int N> __device__ __forceinline__ void cp_wait() {
    asm volatile("cp.async.wait_group %0;" :: "n"(N) : "memory");
}
__device__ __forceinline__ void ldm_x4(uint32_t* d, uint32_t addr) {
    asm volatile("ldmatrix.sync.aligned.m8n8.x4.shared.b16 {%0,%1,%2,%3}, [%4];"
                 : "=r"(d[0]), "=r"(d[1]), "=r"(d[2]), "=r"(d[3]) : "r"(addr));
}
__device__ __forceinline__ void mma16816(float* c, const uint32_t* a, const uint32_t* b) {
    asm volatile(
        "mma.sync.aligned.m16n8k16.row.col.f32.f16.f16.f32 "
        "{%0,%1,%2,%3}, {%4,%5,%6,%7}, {%8,%9}, {%0,%1,%2,%3};"
        : "+f"(c[0]), "+f"(c[1]), "+f"(c[2]), "+f"(c[3])
        : "r"(a[0]), "r"(a[1]), "r"(a[2]), "r"(a[3]), "r"(b[0]), "r"(b[1]));
}
__device__ __forceinline__ uint32_t sw(uint32_t off) {   // XOR-8 swizzle, 128B rows
    return off ^ ((off >> 3) & 0x70);
}

// ---------------------------------------------------------------------------
// K0a: convert enc fp32 -> fp16 (8 elements / thread, 16B stores)
// ---------------------------------------------------------------------------
__global__ void __launch_bounds__(256) convert_enc_kernel(const float4* __restrict__ enc) {
    int i = blockIdx.x * 256 + threadIdx.x;            // over M_*F_/8
    if (i >= M_ * F_ / 8) return;
    float4 v0 = enc[2 * i], v1 = enc[2 * i + 1];
    __half2 h0 = __floats2half2_rn(v0.x, v0.y);
    __half2 h1 = __floats2half2_rn(v0.z, v0.w);
    __half2 h2 = __floats2half2_rn(v1.x, v1.y);
    __half2 h3 = __floats2half2_rn(v1.z, v1.w);
    uint4 u;
    u.x = *(uint32_t*)&h0; u.y = *(uint32_t*)&h1;
    u.z = *(uint32_t*)&h2; u.w = *(uint32_t*)&h3;
    ((uint4*)g_encH)[i] = u;
}

// ---------------------------------------------------------------------------
// K0b: transpose + convert W_enc [K,N] fp32 -> g_WtH [N,K] fp16
// ---------------------------------------------------------------------------
__global__ void __launch_bounds__(256) transpose_kernel(const float* __restrict__ W) {
    __shared__ float t[32][33];
    int k0 = blockIdx.x * 32, n0 = blockIdx.y * 32;
    int x = threadIdx.x;
    for (int y = threadIdx.y; y < 32; y += 8)
        t[y][x] = W[(size_t)(k0 + y) * A_ + n0 + x];
    __syncthreads();
    for (int y = threadIdx.y; y < 32; y += 8)
        g_WtH[(size_t)(n0 + y) * F_ + k0 + x] = __float2half_rn(t[x][y]);
}

// ---------------------------------------------------------------------------
// K1: bias[b,a] = hidden@W_hid + b_hid + b_enc. 16 batches/block.
// grid (A/64=16, B/16=8), block (64,4), dyn smem 64KB.
// ---------------------------------------------------------------------------
__global__ void __launch_bounds__(256) bias_kernel(
    const float* __restrict__ hidden, const float* __restrict__ W_hid,
    const float* __restrict__ b_hid, const float* __restrict__ b_enc)
{
    extern __shared__ float h_s[];              // [16][H_]
    const int a  = blockIdx.x * 64 + threadIdx.x;
    const int b0 = blockIdx.y * 16;
    const int y  = threadIdx.y;
    const int tid = y * 64 + threadIdx.x;

    for (int i = tid; i < 16 * H_; i += 256) {
        int bb = i >> 10, kk = i & (H_ - 1);
        h_s[bb * H_ + kk] = hidden[(b0 + bb) * H_ + kk];
    }
    __syncthreads();

    float acc0 = 0.f, acc1 = 0.f, acc2 = 0.f, acc3 = 0.f;
    const float* wcol = W_hid + a;
    #pragma unroll 8
    for (int k = 0; k < H_; k++) {
        float wv = wcol[(size_t)k * A_];
        acc0 += h_s[(y + 0)  * H_ + k] * wv;
        acc1 += h_s[(y + 4)  * H_ + k] * wv;
        acc2 += h_s[(y + 8)  * H_ + k] * wv;
        acc3 += h_s[(y + 12) * H_ + k] * wv;
    }
    float bb = b_hid[a] + b_enc[a];
    g_bias[(b0 + y + 0)  * A_ + a] = acc0 + bb;
    g_bias[(b0 + y + 4)  * A_ + a] = acc1 + bb;
    g_bias[(b0 + y + 8)  * A_ + a] = acc2 + bb;
    g_bias[(b0 + y + 12) * A_ + a] = acc3 + bb;
}

// ---------------------------------------------------------------------------
// K2: fp16 mma.sync GEMM + relu + W_full reduction.   (FROZEN R12 anchor)
// BM=128, BN=128, BK=64; 256 thr; warps 4(m) x 2(n), 32x64 each; 2 CTA/SM.
// grid (NBLK=8 fastest, 196 m-tiles)
// ---------------------------------------------------------------------------
#define SA(buf)  ((buf) * 16384u)
#define SB(buf)  (32768u + (buf) * 16384u)
#define SM_BIAS  65536
#define SM_WF    66560
#define SM_RED   67072
#define SMEM_BYTES 68096
#define KSTAGES  32            // 2048 / 64

__global__ void __launch_bounds__(256, 2) score_mma_kernel(const float* __restrict__ W_full)
{
    extern __shared__ char smc[];
    const uint32_t sb = smem_u32(smc);
    const int tid  = threadIdx.x;
    const int lane = tid & 31;
    const int wid  = tid >> 5;
    const int wm   = wid & 3;          // 0..3 (M dir)
    const int wn   = wid >> 2;         // 0..1 (N dir)
    const int nblk = blockIdx.x;
    const int m0   = blockIdx.y * 128;
    const int n0   = nblk * 128;

    float* biasf = (float*)(smc + SM_BIAS);   // [2][128]
    float* wff   = (float*)(smc + SM_WF);     // [128]
    float* red   = (float*)(smc + SM_RED);    // [128][2]

    const int b_lo = m0 / L_;
    if (tid < 128) {
        const int b_hi = (m0 + 127) / L_;
        biasf[tid]       = g_bias[b_lo * A_ + n0 + tid];
        biasf[128 + tid] = g_bias[b_hi * A_ + n0 + tid];
        wff[tid]         = W_full[n0 + tid];
    }

    float c[2][8][4];
    #pragma unroll
    for (int t = 0; t < 2; t++)
        #pragma unroll
        for (int j = 0; j < 8; j++)
            #pragma unroll
            for (int q = 0; q < 4; q++) c[t][j][q] = 0.f;

    const __half* aG = g_encH + (size_t)m0 * F_;
    const __half* bG = g_WtH  + (size_t)n0 * F_;

    // --- stage loader: 128 rows x 8 chunks(16B) for A and B, swizzled ---
    auto load_stage = [&](int buf, int s) {
        const int k0 = s * 64;
        #pragma unroll
        for (int r = 0; r < 4; r++) {
            int i = tid + r * 256;
            int row = i >> 3, ch = i & 7;
            uint32_t off = sw((uint32_t)(row * 128 + ch * 16));
            cp16(sb + SA(buf) + off, aG + (size_t)row * F_ + k0 + ch * 8);
        }
        #pragma unroll
        for (int r = 0; r < 4; r++) {
            int i = tid + r * 256;
            int row = i >> 3, ch = i & 7;
            uint32_t off = sw((uint32_t)(row * 128 + ch * 16));
            cp16(sb + SB(buf) + off, bG + (size_t)row * F_ + k0 + ch * 8);
        }
        cp_commit();
    };

    auto compute_stage = [&](int buf) {
        #pragma unroll
        for (int ks = 0; ks < 4; ks++) {
            uint32_t a[2][4];
            #pragma unroll
            for (int t = 0; t < 2; t++) {
                int row = wm * 32 + t * 16 + (lane & 15);
                int ch  = ks * 2 + (lane >> 4);
                a[t][0] = 0;
                ldm_x4(a[t], sb + SA(buf) + sw((uint32_t)(row * 128 + ch * 16)));
            }
            uint32_t bfr[8][2];
            #pragma unroll
            for (int q = 0; q < 4; q++) {
                int row = wn * 64 + q * 16 + ((lane >> 4) << 3) + (lane & 7);
                int ch  = ks * 2 + ((lane >> 3) & 1);
                uint32_t d[4];
                ldm_x4(d, sb + SB(buf) + sw((uint32_t)(row * 128 + ch * 16)));
                bfr[2 * q][0]     = d[0]; bfr[2 * q][1]     = d[1];
                bfr[2 * q + 1][0] = d[2]; bfr[2 * q + 1][1] = d[3];
            }
            #pragma unroll
            for (int t = 0; t < 2; t++)
                #pragma unroll
                for (int j = 0; j < 8; j++)
                    mma16816(c[t][j], a[t], bfr[j]);
        }
    };

    // --- pipeline: double buffer (R8 schedule) ---
    load_stage(0, 0);
    #pragma unroll 1
    for (int s = 0; s < KSTAGES - 1; s++) {
        load_stage((s + 1) & 1, s + 1);
        cp_wait<1>();
        __syncthreads();
        compute_stage(s & 1);
        __syncthreads();
    }
    cp_wait<0>();
    __syncthreads();
    compute_stage((KSTAGES - 1) & 1);

    // --- epilogue: relu(c + bias) * W_full, reduce 128 cols per row ---
    #pragma unroll
    for (int t = 0; t < 2; t++) {
        #pragma unroll
        for (int h = 0; h < 2; h++) {
            int rl  = wm * 32 + (lane >> 2) + t * 16 + h * 8;   // local row
            int sel = ((m0 + rl) / L_ == b_lo) ? 0 : 128;
            float s = 0.f;
            #pragma unroll
            for (int j = 0; j < 8; j++) {
                int col = wn * 64 + j * 8 + (lane & 3) * 2;
                float v0 = c[t][j][2 * h]     + biasf[sel + col];
                float v1 = c[t][j][2 * h + 1] + biasf[sel + col + 1];
                v0 = fmaxf(v0, 0.f); v1 = fmaxf(v1, 0.f);
                s += v0 * wff[col] + v1 * wff[col + 1];
            }
            s += __shfl_xor_sync(0xFFFFFFFFu, s, 1);
            s += __shfl_xor_sync(0xFFFFFFFFu, s, 2);
            if ((lane & 3) == 0) red[rl * 2 + wn] = s;
        }
    }
    __syncthreads();
    if (tid < 128)
        g_part[nblk * M_ + m0 + tid] = red[tid * 2] + red[tid * 2 + 1];
}

// ---------------------------------------------------------------------------
// K3: softmax over L per batch (sums NBLK partials)
// ---------------------------------------------------------------------------
__global__ void __launch_bounds__(256) softmax_kernel(
    const float* __restrict__ b_full, float* __restrict__ alpha)
{
    const int b = blockIdx.x;
    const int t = threadIdx.x;
    __shared__ float red[256];

    float val = 0.f, mval = -1e30f;
    if (t < L_) {
        float acc = b_full[0];
        #pragma unroll
        for (int nb = 0; nb < NBLK; nb++)
            acc += g_part[nb * M_ + b * L_ + t];
        val = acc; mval = acc;
    }
    red[t] = mval; __syncthreads();
    for (int off = 128; off > 0; off >>= 1) {
        if (t < off) red[t] = fmaxf(red[t], red[t + off]);
        __syncthreads();
    }
    float mx = red[0]; __syncthreads();
    float e = (t < L_) ? expf(val - mx) : 0.f;
    red[t] = e; __syncthreads();
    for (int off = 128; off > 0; off >>= 1) {
        if (t < off) red[t] += red[t + off];
        __syncthreads();
    }
    if (t < L_) alpha[b * L_ + t] = e / red[0];
}

// ---------------------------------------------------------------------------
// K4: context[b,f] = sum_l alpha[b,l] * encH[b,l,f]  (fp16 loads, fp32 acc)
// grid (2, B_) = 256 blocks, 256 thr; each thread owns 4 consecutive f.
// ---------------------------------------------------------------------------
__global__ void __launch_bounds__(256) context_kernel(
    const float* __restrict__ alpha, float* __restrict__ ctx)
{
    __shared__ float a_s[L_];
    const int b  = blockIdx.y;
    const int f0 = blockIdx.x * 1024 + threadIdx.x * 4;   // 4 halves per thread
    for (int i = threadIdx.x; i < L_; i += 256)
        a_s[i] = alpha[b * L_ + i];
    __syncthreads();

    const __half* base = g_encH + (size_t)b * L_ * F_ + f0;
    float acc0 = 0.f, acc1 = 0.f, acc2 = 0.f, acc3 = 0.f;
    #pragma unroll 4
    for (int l = 0; l < L_; l++) {
        uint2 u = *(const uint2*)(base + (size_t)l * F_);
        float a = a_s[l];
        float2 p0 = __half22float2(*(__half2*)&u.x);
        float2 p1 = __half22float2(*(__half2*)&u.y);
        acc0 += a * p0.x; acc1 += a * p0.y;
        acc2 += a * p1.x; acc3 += a * p1.y;
    }
    *(float4*)(ctx + (size_t)b * F_ + f0) = make_float4(acc0, acc1, acc2, acc3);
}

// ---------------------------------------------------------------------------
extern "C" void kernel_launch(void* const* d_in, const int* in_sizes, int n_in,
                              void* d_out, int out_size)
{
    const float* enc    = (const float*)d_in[0];
    const float* hidden = (const float*)d_in[1];
    const float* W_enc  = (const float*)d_in[2];
    const float* b_enc  = (const float*)d_in[3];
    const float* W_hid  = (const float*)d_in[4];
    const float* b_hid  = (const float*)d_in[5];
    const float* W_full = (const float*)d_in[6];
    const float* b_full = (const float*)d_in[7];

    float* out   = (float*)d_out;
    float* ctx   = out;             // B*F
    float* alpha = out + B_ * F_;   // B*L

    cudaFuncSetAttribute(score_mma_kernel,
                         cudaFuncAttributeMaxDynamicSharedMemorySize, SMEM_BYTES);
    cudaFuncSetAttribute(bias_kernel,
                         cudaFuncAttributeMaxDynamicSharedMemorySize, 16 * H_ * 4);

    convert_enc_kernel<<<M_ * F_ / 8 / 256, 256>>>((const float4*)enc);
    transpose_kernel<<<dim3(F_ / 32, A_ / 32), dim3(32, 8)>>>(W_enc);
    bias_kernel<<<dim3(A_ / 64, B_ / 16), dim3(64, 4), 16 * H_ * 4>>>(
        hidden, W_hid, b_hid, b_enc);
    score_mma_kernel<<<dim3(NBLK, M_ / 128), 256, SMEM_BYTES>>>(W_full);
    softmax_kernel<<<B_, 256>>>(b_full, alpha);
    context_kernel<<<dim3(2, B_), 256>>>(alpha, ctx);
}

// round 14
// speedup vs baseline: 1.0863x; 1.0863x over previous
#include <cuda_runtime.h>
#include <cuda_fp16.h>
#include <cstdint>
#include <cstddef>

#define B_ 128
#define L_ 196
#define F_ 2048
#define A_ 1024
#define H_ 1024
#define M_ (B_ * L_)   // 25088
#define NBLK 8

// ---------------- scratch (__device__ globals; no allocations) -------------
__device__ float  g_bias[B_ * A_];          // hidden@W_hid + b_hid + b_enc
__device__ float  g_part[NBLK * M_];        // partial scores per n-block
__device__ __half g_encH[M_ * F_];          // enc in fp16 (103 MB)
__device__ __half g_WtH[A_ * F_];           // W_enc^T in fp16, [N][K]

// ---------------- helpers ---------------------------------------------------
__device__ __forceinline__ uint32_t smem_u32(const void* p) {
    uint32_t r;
    asm("{ .reg .u64 t; cvta.to.shared.u64 t, %1; cvt.u32.u64 %0, t; }"
        : "=r"(r) : "l"(p));
    return r;
}
__device__ __forceinline__ void cp16(uint32_t dst, const void* src) {
    asm volatile("cp.async.cg.shared.global [%0], [%1], 16;" :: "r"(dst), "l"(src));
}
__device__ __forceinline__ void cp_commit() {
    asm volatile("cp.async.commit_group;" ::: "memory");
}
template <int N> __device__ __forceinline__ void cp_wait() {
    asm volatile("cp.async.wait_group %0;" :: "n"(N) : "memory");
}
__device__ __forceinline__ void ldm_x4(uint32_t* d, uint32_t addr) {
    asm volatile("ldmatrix.sync.aligned.m8n8.x4.shared.b16 {%0,%1,%2,%3}, [%4];"
                 : "=r"(d[0]), "=r"(d[1]), "=r"(d[2]), "=r"(d[3]) : "r"(addr));
}
__device__ __forceinline__ void mma16816(float* c, const uint32_t* a, const uint32_t* b) {
    asm volatile(
        "mma.sync.aligned.m16n8k16.row.col.f32.f16.f16.f32 "
        "{%0,%1,%2,%3}, {%4,%5,%6,%7}, {%8,%9}, {%0,%1,%2,%3};"
        : "+f"(c[0]), "+f"(c[1]), "+f"(c[2]), "+f"(c[3])
        : "r"(a[0]), "r"(a[1]), "r"(a[2]), "r"(a[3]), "r"(b[0]), "r"(b[1]));
}
__device__ __forceinline__ uint32_t sw(uint32_t off) {   // XOR-8 swizzle, 128B rows
    return off ^ ((off >> 3) & 0x70);
}

// ---------------------------------------------------------------------------
// K0a: convert enc fp32 -> fp16 (8 elements / thread, 16B stores)
// ---------------------------------------------------------------------------
__global__ void __launch_bounds__(256) convert_enc_kernel(const float4* __restrict__ enc) {
    int i = blockIdx.x * 256 + threadIdx.x;            // over M_*F_/8
    if (i >= M_ * F_ / 8) return;
    float4 v0 = enc[2 * i], v1 = enc[2 * i + 1];
    __half2 h0 = __floats2half2_rn(v0.x, v0.y);
    __half2 h1 = __floats2half2_rn(v0.z, v0.w);
    __half2 h2 = __floats2half2_rn(v1.x, v1.y);
    __half2 h3 = __floats2half2_rn(v1.z, v1.w);
    uint4 u;
    u.x = *(uint32_t*)&h0; u.y = *(uint32_t*)&h1;
    u.z = *(uint32_t*)&h2; u.w = *(uint32_t*)&h3;
    ((uint4*)g_encH)[i] = u;
}

// ---------------------------------------------------------------------------
// K0b: transpose + convert W_enc [K,N] fp32 -> g_WtH [N,K] fp16
// ---------------------------------------------------------------------------
__global__ void __launch_bounds__(256) transpose_kernel(const float* __restrict__ W) {
    __shared__ float t[32][33];
    int k0 = blockIdx.x * 32, n0 = blockIdx.y * 32;
    int x = threadIdx.x;
    for (int y = threadIdx.y; y < 32; y += 8)
        t[y][x] = W[(size_t)(k0 + y) * A_ + n0 + x];
    __syncthreads();
    for (int y = threadIdx.y; y < 32; y += 8)
        g_WtH[(size_t)(n0 + y) * F_ + k0 + x] = __float2half_rn(t[x][y]);
}

// ---------------------------------------------------------------------------
// K1: bias[b,a] = hidden@W_hid + b_hid + b_enc   (fp32)  -- R12 version
// ---------------------------------------------------------------------------
__global__ void __launch_bounds__(256) bias_kernel(
    const float* __restrict__ hidden, const float* __restrict__ W_hid,
    const float* __restrict__ b_hid, const float* __restrict__ b_enc)
{
    __shared__ float h_s[4][H_];
    int a  = blockIdx.x * 64 + threadIdx.x;
    int b0 = blockIdx.y * 4;
    int tid = threadIdx.y * 64 + threadIdx.x;
    for (int i = tid; i < 4 * H_; i += 256) {
        int bb = i >> 10, kk = i & (H_ - 1);
        h_s[bb][kk] = hidden[(b0 + bb) * H_ + kk];
    }
    __syncthreads();
    float acc = 0.f;
    const float* wcol = W_hid + a;
    #pragma unroll 8
    for (int k = 0; k < H_; k++)
        acc += h_s[threadIdx.y][k] * wcol[(size_t)k * A_];
    int b = b0 + threadIdx.y;
    g_bias[b * A_ + a] = acc + b_hid[a] + b_enc[a];
}

// ---------------------------------------------------------------------------
// K2: fp16 mma.sync GEMM + relu + W_full reduction.
// BM=128, BN=128, BK=64; 256 thr; warps 4(m) x 2(n), 32x64 each; 2 CTA/SM.
// ONLY change vs R12: 3-stage cp.async pipeline, static buffer indices,
// one __syncthreads per stage.
// grid (NBLK=8 fastest, 196 m-tiles)
// ---------------------------------------------------------------------------
#define SA(buf)  ((buf) * 16384u)               // 3 x 16KB
#define SB(buf)  (49152u + (buf) * 16384u)      // 3 x 16KB
#define SM_BIAS  98304
#define SM_WF    99328
#define SM_RED   99840
#define SMEM_BYTES 100864
#define KSTAGES  32            // 2048 / 64

__global__ void __launch_bounds__(256, 2) score_mma_kernel(const float* __restrict__ W_full)
{
    extern __shared__ char smc[];
    const uint32_t sb = smem_u32(smc);
    const int tid  = threadIdx.x;
    const int lane = tid & 31;
    const int wid  = tid >> 5;
    const int wm   = wid & 3;          // 0..3 (M dir)
    const int wn   = wid >> 2;         // 0..1 (N dir)
    const int nblk = blockIdx.x;
    const int m0   = blockIdx.y * 128;
    const int n0   = nblk * 128;

    float* biasf = (float*)(smc + SM_BIAS);   // [2][128]
    float* wff   = (float*)(smc + SM_WF);     // [128]
    float* red   = (float*)(smc + SM_RED);    // [128][2]

    const int b_lo = m0 / L_;
    if (tid < 128) {
        const int b_hi = (m0 + 127) / L_;
        biasf[tid]       = g_bias[b_lo * A_ + n0 + tid];
        biasf[128 + tid] = g_bias[b_hi * A_ + n0 + tid];
        wff[tid]         = W_full[n0 + tid];
    }

    float c[2][8][4];
    #pragma unroll
    for (int t = 0; t < 2; t++)
        #pragma unroll
        for (int j = 0; j < 8; j++)
            #pragma unroll
            for (int q = 0; q < 4; q++) c[t][j][q] = 0.f;

    const __half* aG = g_encH + (size_t)m0 * F_;
    const __half* bG = g_WtH  + (size_t)n0 * F_;

    // --- stage loader: 128 rows x 8 chunks(16B) for A and B, swizzled ---
    auto load_stage = [&](int buf, int s) {
        const int k0 = s * 64;
        #pragma unroll
        for (int r = 0; r < 4; r++) {
            int i = tid + r * 256;
            int row = i >> 3, ch = i & 7;
            uint32_t off = sw((uint32_t)(row * 128 + ch * 16));
            cp16(sb + SA(buf) + off, aG + (size_t)row * F_ + k0 + ch * 8);
        }
        #pragma unroll
        for (int r = 0; r < 4; r++) {
            int i = tid + r * 256;
            int row = i >> 3, ch = i & 7;
            uint32_t off = sw((uint32_t)(row * 128 + ch * 16));
            cp16(sb + SB(buf) + off, bG + (size_t)row * F_ + k0 + ch * 8);
        }
        cp_commit();
    };

    auto compute_stage = [&](int buf) {
        #pragma unroll
        for (int ks = 0; ks < 4; ks++) {
            uint32_t a[2][4];
            #pragma unroll
            for (int t = 0; t < 2; t++) {
                int row = wm * 32 + t * 16 + (lane & 15);
                int ch  = ks * 2 + (lane >> 4);
                a[t][0] = 0;
                ldm_x4(a[t], sb + SA(buf) + sw((uint32_t)(row * 128 + ch * 16)));
            }
            uint32_t bfr[8][2];
            #pragma unroll
            for (int q = 0; q < 4; q++) {
                int row = wn * 64 + q * 16 + ((lane >> 4) << 3) + (lane & 7);
                int ch  = ks * 2 + ((lane >> 3) & 1);
                uint32_t d[4];
                ldm_x4(d, sb + SB(buf) + sw((uint32_t)(row * 128 + ch * 16)));
                bfr[2 * q][0]     = d[0]; bfr[2 * q][1]     = d[1];
                bfr[2 * q + 1][0] = d[2]; bfr[2 * q + 1][1] = d[3];
            }
            #pragma unroll
            for (int t = 0; t < 2; t++)
                #pragma unroll
                for (int j = 0; j < 8; j++)
                    mma16816(c[t][j], a[t], bfr[j]);
        }
    };

    // --- 3-stage pipeline, static buffer indices, one sync per stage ---
    // invariant entering stage s: groups s, s+1 issued (2 pending).
    // cp_wait<1> -> stage s landed; barrier separates compute(s-1) from
    // load(s+2) which reuses buffer (s-1)%3.
    load_stage(0, 0);
    load_stage(1, 1);
    #pragma unroll 1
    for (int st = 0; st < 30; st += 3) {
        cp_wait<1>(); __syncthreads();
        if (st + 2 < KSTAGES) load_stage(2, st + 2);
        compute_stage(0);

        cp_wait<1>(); __syncthreads();
        if (st + 3 < KSTAGES) load_stage(0, st + 3);
        compute_stage(1);

        cp_wait<1>(); __syncthreads();
        if (st + 4 < KSTAGES) load_stage(1, st + 4);
        compute_stage(2);
    }
    // s = 30 (buf 0), s = 31 (buf 1); no more loads
    cp_wait<1>(); __syncthreads();
    compute_stage(0);
    cp_wait<0>(); __syncthreads();
    compute_stage(1);

    // --- epilogue: relu(c + bias) * W_full, reduce 128 cols per row ---
    #pragma unroll
    for (int t = 0; t < 2; t++) {
        #pragma unroll
        for (int h = 0; h < 2; h++) {
            int rl  = wm * 32 + (lane >> 2) + t * 16 + h * 8;   // local row
            int sel = ((m0 + rl) / L_ == b_lo) ? 0 : 128;
            float s = 0.f;
            #pragma unroll
            for (int j = 0; j < 8; j++) {
                int col = wn * 64 + j * 8 + (lane & 3) * 2;
                float v0 = c[t][j][2 * h]     + biasf[sel + col];
                float v1 = c[t][j][2 * h + 1] + biasf[sel + col + 1];
                v0 = fmaxf(v0, 0.f); v1 = fmaxf(v1, 0.f);
                s += v0 * wff[col] + v1 * wff[col + 1];
            }
            s += __shfl_xor_sync(0xFFFFFFFFu, s, 1);
            s += __shfl_xor_sync(0xFFFFFFFFu, s, 2);
            if ((lane & 3) == 0) red[rl * 2 + wn] = s;
        }
    }
    __syncthreads();
    if (tid < 128)
        g_part[nblk * M_ + m0 + tid] = red[tid * 2] + red[tid * 2 + 1];
}

// ---------------------------------------------------------------------------
// K3: softmax over L per batch (sums NBLK partials)
// ---------------------------------------------------------------------------
__global__ void __launch_bounds__(256) softmax_kernel(
    const float* __restrict__ b_full, float* __restrict__ alpha)
{
    const int b = blockIdx.x;
    const int t = threadIdx.x;
    __shared__ float red[256];

    float val = 0.f, mval = -1e30f;
    if (t < L_) {
        float acc = b_full[0];
        #pragma unroll
        for (int nb = 0; nb < NBLK; nb++)
            acc += g_part[nb * M_ + b * L_ + t];
        val = acc; mval = acc;
    }
    red[t] = mval; __syncthreads();
    for (int off = 128; off > 0; off >>= 1) {
        if (t < off) red[t] = fmaxf(red[t], red[t + off]);
        __syncthreads();
    }
    float mx = red[0]; __syncthreads();
    float e = (t < L_) ? expf(val - mx) : 0.f;
    red[t] = e; __syncthreads();
    for (int off = 128; off > 0; off >>= 1) {
        if (t < off) red[t] += red[t + off];
        __syncthreads();
    }
    if (t < L_) alpha[b * L_ + t] = e / red[0];
}

// ---------------------------------------------------------------------------
// K4: context[b,f] = sum_l alpha[b,l] * enc[b,l,f]   (fp32 enc, float4)
// ---------------------------------------------------------------------------
__global__ void __launch_bounds__(256) context_kernel(
    const float* __restrict__ enc, const float* __restrict__ alpha,
    float* __restrict__ ctx)
{
    __shared__ float a_s[L_];
    const int b  = blockIdx.y;
    const int f4 = blockIdx.x * 256 + threadIdx.x;   // 512 float4 per batch row
    for (int i = threadIdx.x; i < L_; i += 256)
        a_s[i] = alpha[b * L_ + i];
    __syncthreads();

    const float4* p = (const float4*)(enc + (size_t)b * L_ * F_) + f4;
    float4 acc = make_float4(0.f, 0.f, 0.f, 0.f);
    #pragma unroll 4
    for (int l = 0; l < L_; l++) {
        float4 v = p[(size_t)l * (F_ / 4)];
        float a = a_s[l];
        acc.x += a * v.x; acc.y += a * v.y; acc.z += a * v.z; acc.w += a * v.w;
    }
    ((float4*)ctx)[b * (F_ / 4) + f4] = acc;
}

// ---------------------------------------------------------------------------
extern "C" void kernel_launch(void* const* d_in, const int* in_sizes, int n_in,
                              void* d_out, int out_size)
{
    const float* enc    = (const float*)d_in[0];
    const float* hidden = (const float*)d_in[1];
    const float* W_enc  = (const float*)d_in[2];
    const float* b_enc  = (const float*)d_in[3];
    const float* W_hid  = (const float*)d_in[4];
    const float* b_hid  = (const float*)d_in[5];
    const float* W_full = (const float*)d_in[6];
    const float* b_full = (const float*)d_in[7];

    float* out   = (float*)d_out;
    float* ctx   = out;             // B*F
    float* alpha = out + B_ * F_;   // B*L

    cudaFuncSetAttribute(score_mma_kernel,
                         cudaFuncAttributeMaxDynamicSharedMemorySize, SMEM_BYTES);

    convert_enc_kernel<<<M_ * F_ / 8 / 256, 256>>>((const float4*)enc);
    transpose_kernel<<<dim3(F_ / 32, A_ / 32), dim3(32, 8)>>>(W_enc);
    bias_kernel<<<dim3(A_ / 64, B_ / 4), dim3(64, 4)>>>(hidden, W_hid, b_hid, b_enc);
    score_mma_kernel<<<dim3(NBLK, M_ / 128), 256, SMEM_BYTES>>>(W_full);
    softmax_kernel<<<B_, 256>>>(b_full, alpha);
    context_kernel<<<dim3(2, B_), 256>>>(enc, alpha, ctx);
}

// round 15
// speedup vs baseline: 1.1192x; 1.0304x over previous
#include <cuda_runtime.h>
#include <cuda_fp16.h>
#include <cstdint>
#include <cstddef>

#define B_ 128
#define L_ 196
#define F_ 2048
#define A_ 1024
#define H_ 1024
#define M_ (B_ * L_)   // 25088
#define NBLK 8

// ---------------- scratch (__device__ globals; no allocations) -------------
__device__ float  g_bias[B_ * A_];          // hidden@W_hid + b_hid + b_enc
__device__ float  g_part[NBLK * M_];        // partial scores per n-block
__device__ __half g_encH[M_ * F_];          // enc in fp16 (103 MB)
__device__ __half g_WtH[A_ * F_];           // W_enc^T in fp16, [N][K]

// ---------------- helpers ---------------------------------------------------
__device__ __forceinline__ uint32_t smem_u32(const void* p) {
    uint32_t r;
    asm("{ .reg .u64 t; cvta.to.shared.u64 t, %1; cvt.u32.u64 %0, t; }"
        : "=r"(r) : "l"(p));
    return r;
}
__device__ __forceinline__ void cp16(uint32_t dst, const void* src) {
    asm volatile("cp.async.cg.shared.global [%0], [%1], 16;" :: "r"(dst), "l"(src));
}
__device__ __forceinline__ void cp_commit() {
    asm volatile("cp.async.commit_group;" ::: "memory");
}
template <int N> __device__ __forceinline__ void cp_wait() {
    asm volatile("cp.async.wait_group %0;" :: "n"(N) : "memory");
}
__device__ __forceinline__ void ldm_x4(uint32_t* d, uint32_t addr) {
    asm volatile("ldmatrix.sync.aligned.m8n8.x4.shared.b16 {%0,%1,%2,%3}, [%4];"
                 : "=r"(d[0]), "=r"(d[1]), "=r"(d[2]), "=r"(d[3]) : "r"(addr));
}
__device__ __forceinline__ void mma16816(float* c, const uint32_t* a, const uint32_t* b) {
    asm volatile(
        "mma.sync.aligned.m16n8k16.row.col.f32.f16.f16.f32 "
        "{%0,%1,%2,%3}, {%4,%5,%6,%7}, {%8,%9}, {%0,%1,%2,%3};"
        : "+f"(c[0]), "+f"(c[1]), "+f"(c[2]), "+f"(c[3])
        : "r"(a[0]), "r"(a[1]), "r"(a[2]), "r"(a[3]), "r"(b[0]), "r"(b[1]));
}
__device__ __forceinline__ uint32_t sw(uint32_t off) {   // XOR-8 swizzle, 128B rows
    return off ^ ((off >> 3) & 0x70);
}

// ---------------------------------------------------------------------------
// K0a: convert enc fp32 -> fp16 (8 elements / thread, 16B stores)
// ---------------------------------------------------------------------------
__global__ void __launch_bounds__(256) convert_enc_kernel(const float4* __restrict__ enc) {
    int i = blockIdx.x * 256 + threadIdx.x;            // over M_*F_/8
    if (i >= M_ * F_ / 8) return;
    float4 v0 = enc[2 * i], v1 = enc[2 * i + 1];
    __half2 h0 = __floats2half2_rn(v0.x, v0.y);
    __half2 h1 = __floats2half2_rn(v0.z, v0.w);
    __half2 h2 = __floats2half2_rn(v1.x, v1.y);
    __half2 h3 = __floats2half2_rn(v1.z, v1.w);
    uint4 u;
    u.x = *(uint32_t*)&h0; u.y = *(uint32_t*)&h1;
    u.z = *(uint32_t*)&h2; u.w = *(uint32_t*)&h3;
    ((uint4*)g_encH)[i] = u;
}

// ---------------------------------------------------------------------------
// K0b: transpose + convert W_enc [K,N] fp32 -> g_WtH [N,K] fp16
// ---------------------------------------------------------------------------
__global__ void __launch_bounds__(256) transpose_kernel(const float* __restrict__ W) {
    __shared__ float t[32][33];
    int k0 = blockIdx.x * 32, n0 = blockIdx.y * 32;
    int x = threadIdx.x;
    for (int y = threadIdx.y; y < 32; y += 8)
        t[y][x] = W[(size_t)(k0 + y) * A_ + n0 + x];
    __syncthreads();
    for (int y = threadIdx.y; y < 32; y += 8)
        g_WtH[(size_t)(n0 + y) * F_ + k0 + x] = __float2half_rn(t[x][y]);
}

// ---------------------------------------------------------------------------
// K1: bias[b,a] = hidden@W_hid + b_hid + b_enc   (fp32)  -- R12 version
// ---------------------------------------------------------------------------
__global__ void __launch_bounds__(256) bias_kernel(
    const float* __restrict__ hidden, const float* __restrict__ W_hid,
    const float* __restrict__ b_hid, const float* __restrict__ b_enc)
{
    __shared__ float h_s[4][H_];
    int a  = blockIdx.x * 64 + threadIdx.x;
    int b0 = blockIdx.y * 4;
    int tid = threadIdx.y * 64 + threadIdx.x;
    for (int i = tid; i < 4 * H_; i += 256) {
        int bb = i >> 10, kk = i & (H_ - 1);
        h_s[bb][kk] = hidden[(b0 + bb) * H_ + kk];
    }
    __syncthreads();
    float acc = 0.f;
    const float* wcol = W_hid + a;
    #pragma unroll 8
    for (int k = 0; k < H_; k++)
        acc += h_s[threadIdx.y][k] * wcol[(size_t)k * A_];
    int b = b0 + threadIdx.y;
    g_bias[b * A_ + a] = acc + b_hid[a] + b_enc[a];
}

// ---------------------------------------------------------------------------
// K2: fp16 mma.sync GEMM + relu + W_full reduction.
// ONLY change vs R12: BM 128 -> 64. BM=64, BN=128, BK=64; 128 thr;
// warps 2(m) x 2(n), warp tile 32x64 (identical microkernel); double buffer;
// 4 CTAs/SM. grid (NBLK=8 fastest, 392 m-tiles) -> finer wave quantization.
// ---------------------------------------------------------------------------
#define SA(buf)  ((buf) * 8192u)                // 2 x 8KB  (A: 64 x 128B)
#define SB(buf)  (16384u + (buf) * 16384u)      // 2 x 16KB (B: 128 x 128B)
#define SM_BIAS  49152
#define SM_WF    50176
#define SM_RED   50688
#define SMEM_BYTES 51200
#define KSTAGES  32            // 2048 / 64

__global__ void __launch_bounds__(128, 4) score_mma_kernel(const float* __restrict__ W_full)
{
    extern __shared__ char smc[];
    const uint32_t sb = smem_u32(smc);
    const int tid  = threadIdx.x;
    const int lane = tid & 31;
    const int wid  = tid >> 5;
    const int wm   = wid & 1;          // 0..1 (M dir)
    const int wn   = wid >> 1;         // 0..1 (N dir)
    const int nblk = blockIdx.x;
    const int m0   = blockIdx.y * 64;
    const int n0   = nblk * 128;

    float* biasf = (float*)(smc + SM_BIAS);   // [2][128]
    float* wff   = (float*)(smc + SM_WF);     // [128]
    float* red   = (float*)(smc + SM_RED);    // [64][2]

    const int b_lo = m0 / L_;
    const int b_hi = (m0 + 63) / L_;
    if (tid < 128) {
        biasf[tid]       = g_bias[b_lo * A_ + n0 + tid];
        biasf[128 + tid] = g_bias[b_hi * A_ + n0 + tid];
        wff[tid]         = W_full[n0 + tid];
    }

    float c[2][8][4];
    #pragma unroll
    for (int t = 0; t < 2; t++)
        #pragma unroll
        for (int j = 0; j < 8; j++)
            #pragma unroll
            for (int q = 0; q < 4; q++) c[t][j][q] = 0.f;

    const __half* aG = g_encH + (size_t)m0 * F_;
    const __half* bG = g_WtH  + (size_t)n0 * F_;

    // --- stage loader: A 64 rows, B 128 rows; 8 chunks(16B)/row, swizzled ---
    auto load_stage = [&](int buf, int s) {
        const int k0 = s * 64;
        #pragma unroll
        for (int r = 0; r < 4; r++) {              // A: 512 chunks / 128 thr
            int i = tid + r * 128;
            int row = i >> 3, ch = i & 7;
            uint32_t off = sw((uint32_t)(row * 128 + ch * 16));
            cp16(sb + SA(buf) + off, aG + (size_t)row * F_ + k0 + ch * 8);
        }
        #pragma unroll
        for (int r = 0; r < 8; r++) {              // B: 1024 chunks / 128 thr
            int i = tid + r * 128;
            int row = i >> 3, ch = i & 7;
            uint32_t off = sw((uint32_t)(row * 128 + ch * 16));
            cp16(sb + SB(buf) + off, bG + (size_t)row * F_ + k0 + ch * 8);
        }
        cp_commit();
    };

    auto compute_stage = [&](int buf) {
        #pragma unroll
        for (int ks = 0; ks < 4; ks++) {
            uint32_t a[2][4];
            #pragma unroll
            for (int t = 0; t < 2; t++) {
                int row = wm * 32 + t * 16 + (lane & 15);
                int ch  = ks * 2 + (lane >> 4);
                ldm_x4(a[t], sb + SA(buf) + sw((uint32_t)(row * 128 + ch * 16)));
            }
            uint32_t bfr[8][2];
            #pragma unroll
            for (int q = 0; q < 4; q++) {
                int row = wn * 64 + q * 16 + ((lane >> 4) << 3) + (lane & 7);
                int ch  = ks * 2 + ((lane >> 3) & 1);
                uint32_t d[4];
                ldm_x4(d, sb + SB(buf) + sw((uint32_t)(row * 128 + ch * 16)));
                bfr[2 * q][0]     = d[0]; bfr[2 * q][1]     = d[1];
                bfr[2 * q + 1][0] = d[2]; bfr[2 * q + 1][1] = d[3];
            }
            #pragma unroll
            for (int t = 0; t < 2; t++)
                #pragma unroll
                for (int j = 0; j < 8; j++)
                    mma16816(c[t][j], a[t], bfr[j]);
        }
    };

    // --- pipeline: double buffer (R12 schedule) ---
    load_stage(0, 0);
    #pragma unroll 1
    for (int s = 0; s < KSTAGES - 1; s++) {
        load_stage((s + 1) & 1, s + 1);
        cp_wait<1>();
        __syncthreads();
        compute_stage(s & 1);
        __syncthreads();
    }
    cp_wait<0>();
    __syncthreads();
    compute_stage((KSTAGES - 1) & 1);

    // --- epilogue: relu(c + bias) * W_full, reduce 128 cols per row ---
    #pragma unroll
    for (int t = 0; t < 2; t++) {
        #pragma unroll
        for (int h = 0; h < 2; h++) {
            int rl  = wm * 32 + (lane >> 2) + t * 16 + h * 8;   // local row 0..63
            int sel = ((m0 + rl) / L_ == b_lo) ? 0 : 128;
            float s = 0.f;
            #pragma unroll
            for (int j = 0; j < 8; j++) {
                int col = wn * 64 + j * 8 + (lane & 3) * 2;
                float v0 = c[t][j][2 * h]     + biasf[sel + col];
                float v1 = c[t][j][2 * h + 1] + biasf[sel + col + 1];
                v0 = fmaxf(v0, 0.f); v1 = fmaxf(v1, 0.f);
                s += v0 * wff[col] + v1 * wff[col + 1];
            }
            s += __shfl_xor_sync(0xFFFFFFFFu, s, 1);
            s += __shfl_xor_sync(0xFFFFFFFFu, s, 2);
            if ((lane & 3) == 0) red[rl * 2 + wn] = s;
        }
    }
    __syncthreads();
    if (tid < 64)
        g_part[nblk * M_ + m0 + tid] = red[tid * 2] + red[tid * 2 + 1];
}

// ---------------------------------------------------------------------------
// K3: softmax over L per batch (sums NBLK partials)
// ---------------------------------------------------------------------------
__global__ void __launch_bounds__(256) softmax_kernel(
    const float* __restrict__ b_full, float* __restrict__ alpha)
{
    const int b = blockIdx.x;
    const int t = threadIdx.x;
    __shared__ float red[256];

    float val = 0.f, mval = -1e30f;
    if (t < L_) {
        float acc = b_full[0];
        #pragma unroll
        for (int nb = 0; nb < NBLK; nb++)
            acc += g_part[nb * M_ + b * L_ + t];
        val = acc; mval = acc;
    }
    red[t] = mval; __syncthreads();
    for (int off = 128; off > 0; off >>= 1) {
        if (t < off) red[t] = fmaxf(red[t], red[t + off]);
        __syncthreads();
    }
    float mx = red[0]; __syncthreads();
    float e = (t < L_) ? expf(val - mx) : 0.f;
    red[t] = e; __syncthreads();
    for (int off = 128; off > 0; off >>= 1) {
        if (t < off) red[t] += red[t + off];
        __syncthreads();
    }
    if (t < L_) alpha[b * L_ + t] = e / red[0];
}

// ---------------------------------------------------------------------------
// K4: context[b,f] = sum_l alpha[b,l] * enc[b,l,f]   (fp32 enc, float4)
// ---------------------------------------------------------------------------
__global__ void __launch_bounds__(256) context_kernel(
    const float* __restrict__ enc, const float* __restrict__ alpha,
    float* __restrict__ ctx)
{
    __shared__ float a_s[L_];
    const int b  = blockIdx.y;
    const int f4 = blockIdx.x * 256 + threadIdx.x;   // 512 float4 per batch row
    for (int i = threadIdx.x; i < L_; i += 256)
        a_s[i] = alpha[b * L_ + i];
    __syncthreads();

    const float4* p = (const float4*)(enc + (size_t)b * L_ * F_) + f4;
    float4 acc = make_float4(0.f, 0.f, 0.f, 0.f);
    #pragma unroll 4
    for (int l = 0; l < L_; l++) {
        float4 v = p[(size_t)l * (F_ / 4)];
        float a = a_s[l];
        acc.x += a * v.x; acc.y += a * v.y; acc.z += a * v.z; acc.w += a * v.w;
    }
    ((float4*)ctx)[b * (F_ / 4) + f4] = acc;
}

// ---------------------------------------------------------------------------
extern "C" void kernel_launch(void* const* d_in, const int* in_sizes, int n_in,
                              void* d_out, int out_size)
{
    const float* enc    = (const float*)d_in[0];
    const float* hidden = (const float*)d_in[1];
    const float* W_enc  = (const float*)d_in[2];
    const float* b_enc  = (const float*)d_in[3];
    const float* W_hid  = (const float*)d_in[4];
    const float* b_hid  = (const float*)d_in[5];
    const float* W_full = (const float*)d_in[6];
    const float* b_full = (const float*)d_in[7];

    float* out   = (float*)d_out;
    float* ctx   = out;             // B*F
    float* alpha = out + B_ * F_;   // B*L

    cudaFuncSetAttribute(score_mma_kernel,
                         cudaFuncAttributeMaxDynamicSharedMemorySize, SMEM_BYTES);

    convert_enc_kernel<<<M_ * F_ / 8 / 256, 256>>>((const float4*)enc);
    transpose_kernel<<<dim3(F_ / 32, A_ / 32), dim3(32, 8)>>>(W_enc);
    bias_kernel<<<dim3(A_ / 64, B_ / 4), dim3(64, 4)>>>(hidden, W_hid, b_hid, b_enc);
    score_mma_kernel<<<dim3(NBLK, M_ / 64), 128, SMEM_BYTES>>>(W_full);
    softmax_kernel<<<B_, 256>>>(b_full, alpha);
    context_kernel<<<dim3(2, B_), 256>>>(enc, alpha, ctx);
}